// round 1
// baseline (speedup 1.0000x reference)
#include <cuda_runtime.h>

#define NNODE 50000
#define HDIM  128
#define GNUM  64
#define EPSBN 1e-5f

// ---------------- device scratch (no allocs allowed) ----------------
__device__ float g_K [NNODE * HDIM];
__device__ float g_Q [NNODE * HDIM];
__device__ float g_V [NNODE * HDIM];
__device__ float g_H0[NNODE * HDIM];
__device__ float g_H1[NNODE * HDIM];
__device__ float g_pool[GNUM * 2 * HDIM];
__device__ float g_h1m[GNUM * HDIM];
__device__ float g_h2m[GNUM * (HDIM / 2)];

// ---------------- fused 4-way GEMM: {K,Q,V,S} = X @ W^T + b ----------------
// BM=128, BN=64 (blockIdx.y: 8 tiles over 4 output buffers), BK=16, 256 thr,
// 8x4 register micro-tile.
template <bool RELU_IN>
__global__ __launch_bounds__(256) void gemm4_kernel(
    const float* __restrict__ X,
    const float* __restrict__ Wk, const float* __restrict__ Wq,
    const float* __restrict__ Wv, const float* __restrict__ Ws,
    const float* __restrict__ bk, const float* __restrict__ bq,
    const float* __restrict__ bv, const float* __restrict__ bs,
    float* __restrict__ oK, float* __restrict__ oQ,
    float* __restrict__ oV, float* __restrict__ oS, int N)
{
    const int sel = blockIdx.y >> 1;
    const float* W    = (sel == 0) ? Wk : (sel == 1) ? Wq : (sel == 2) ? Wv : Ws;
    const float* bias = (sel == 0) ? bk : (sel == 1) ? bq : (sel == 2) ? bv : bs;
    float*       out  = (sel == 0) ? oK : (sel == 1) ? oQ : (sel == 2) ? oV : oS;
    const int n0 = (blockIdx.y & 1) * 64;
    const int m0 = blockIdx.x * 128;

    __shared__ float As[16][132];
    __shared__ float Bs[16][68];

    const int tid = threadIdx.x;
    const int tx = tid & 15;   // 0..15 -> 4 output cols each
    const int ty = tid >> 4;   // 0..15 -> 8 output rows each

    float acc[8][4];
#pragma unroll
    for (int i = 0; i < 8; i++)
#pragma unroll
        for (int j = 0; j < 4; j++) acc[i][j] = 0.f;

    const int ar = tid >> 1;        // 0..127
    const int ac = (tid & 1) * 8;   // 0 or 8
    const int br = tid >> 2;        // 0..63
    const int bc = (tid & 3) * 4;   // 0,4,8,12

    for (int ko = 0; ko < HDIM; ko += 16) {
        const int gm = m0 + ar;
#pragma unroll
        for (int h = 0; h < 2; h++) {
            const int c = ac + h * 4;
            float4 a = make_float4(0.f, 0.f, 0.f, 0.f);
            if (gm < N) a = *(const float4*)(X + (long)gm * HDIM + ko + c);
            if (RELU_IN) {
                a.x = fmaxf(a.x, 0.f); a.y = fmaxf(a.y, 0.f);
                a.z = fmaxf(a.z, 0.f); a.w = fmaxf(a.w, 0.f);
            }
            As[c + 0][ar] = a.x; As[c + 1][ar] = a.y;
            As[c + 2][ar] = a.z; As[c + 3][ar] = a.w;
        }
        {
            const float4 b = *(const float4*)(W + (long)(n0 + br) * HDIM + ko + bc);
            Bs[bc + 0][br] = b.x; Bs[bc + 1][br] = b.y;
            Bs[bc + 2][br] = b.z; Bs[bc + 3][br] = b.w;
        }
        __syncthreads();
#pragma unroll
        for (int kk = 0; kk < 16; kk++) {
            const float4 a0 = *(const float4*)&As[kk][ty * 8];
            const float4 a1 = *(const float4*)&As[kk][ty * 8 + 4];
            const float4 b0 = *(const float4*)&Bs[kk][tx * 4];
            const float a[8] = {a0.x, a0.y, a0.z, a0.w, a1.x, a1.y, a1.z, a1.w};
            const float b[4] = {b0.x, b0.y, b0.z, b0.w};
#pragma unroll
            for (int i = 0; i < 8; i++)
#pragma unroll
                for (int j = 0; j < 4; j++) acc[i][j] += a[i] * b[j];
        }
        __syncthreads();
    }

    float bb[4];
#pragma unroll
    for (int j = 0; j < 4; j++) bb[j] = bias[n0 + tx * 4 + j];
#pragma unroll
    for (int i = 0; i < 8; i++) {
        const int gm = m0 + ty * 8 + i;
        if (gm < N) {
            float4 r;
            r.x = acc[i][0] + bb[0];
            r.y = acc[i][1] + bb[1];
            r.z = acc[i][2] + bb[2];
            r.w = acc[i][3] + bb[3];
            *(float4*)(out + (long)gm * HDIM + n0 + tx * 4) = r;
        }
    }
}

// ---------------- edge kernel: agg[dst] += sigmoid(K[dst]+Q[src]) * V[src] --
__global__ __launch_bounds__(256) void edge_kernel(
    const int* __restrict__ ei, int E,
    const float* __restrict__ K, const float* __restrict__ Q,
    const float* __restrict__ V, float* __restrict__ AGG)
{
    const int warp = (blockIdx.x * blockDim.x + threadIdx.x) >> 5;
    const int lane = threadIdx.x & 31;
    if (warp >= E) return;
    const int s = ei[warp];
    const int d = ei[E + warp];

    const float4 k4 = *(const float4*)(K + (long)d * HDIM + lane * 4);
    const float4 q4 = *(const float4*)(Q + (long)s * HDIM + lane * 4);
    const float4 v4 = *(const float4*)(V + (long)s * HDIM + lane * 4);

    float* o = AGG + (long)d * HDIM + lane * 4;
    const float g0 = 1.f / (1.f + __expf(-(k4.x + q4.x)));
    const float g1 = 1.f / (1.f + __expf(-(k4.y + q4.y)));
    const float g2 = 1.f / (1.f + __expf(-(k4.z + q4.z)));
    const float g3 = 1.f / (1.f + __expf(-(k4.w + q4.w)));
    atomicAdd(o + 0, g0 * v4.x);
    atomicAdd(o + 1, g1 * v4.y);
    atomicAdd(o + 2, g2 * v4.z);
    atomicAdd(o + 3, g3 * v4.w);
}

// ---------------- pooling: batch_index is sorted -> binary search segment ---
__device__ __forceinline__ int lower_bound_i(const int* a, int n, int v) {
    int lo = 0, hi = n;
    while (lo < hi) { int m = (lo + hi) >> 1; if (a[m] < v) lo = m + 1; else hi = m; }
    return lo;
}

__global__ void pool_kernel(const float* __restrict__ H,
                            const int* __restrict__ batch, int N,
                            float* __restrict__ pool)
{
    const int g = blockIdx.x;       // 64 graphs
    const int c = threadIdx.x;      // 128 columns
    const int lo = lower_bound_i(batch, N, g);
    const int hi = lower_bound_i(batch, N, g + 1);
    float mx = -3.402823466e38f;
    float sm = 0.f;
    for (int n = lo; n < hi; n++) {
        const float x = H[(long)n * HDIM + c];
        mx = fmaxf(mx, x);
        sm += x;
    }
    const int cnt = hi - lo;
    pool[g * (2 * HDIM) + c]        = (cnt > 0) ? mx : 0.f;
    pool[g * (2 * HDIM) + HDIM + c] = sm / fmaxf((float)cnt, 1.f);
}

// ---------------- MLP head: per-column blocks (BN is per-column) -----------
// h1[r][c] = relu(BN(pool[r] . W1[c] + b1[c]))   — 128 blocks x 64 threads
__global__ void mlp1_kernel(const float* __restrict__ pool,
                            const float* __restrict__ W1, const float* __restrict__ b1,
                            const float* __restrict__ g1, const float* __restrict__ be1,
                            float* __restrict__ h1)
{
    const int c = blockIdx.x;   // 0..127
    const int r = threadIdx.x;  // 0..63
    float acc = b1[c];
    const float* w = W1 + (long)c * (2 * HDIM);
    const float* f = pool + (long)r * (2 * HDIM);
#pragma unroll 8
    for (int i = 0; i < 2 * HDIM; i++) acc += f[i] * w[i];

    __shared__ float red[GNUM];
    red[r] = acc; __syncthreads();
    float m = 0.f;
    if (r == 0) { for (int i = 0; i < GNUM; i++) m += red[i]; red[0] = m / GNUM; }
    __syncthreads();
    m = red[0]; __syncthreads();
    red[r] = (acc - m) * (acc - m); __syncthreads();
    float v = 0.f;
    if (r == 0) { for (int i = 0; i < GNUM; i++) v += red[i]; red[0] = v / GNUM; }
    __syncthreads();
    v = red[0];
    const float y = g1[c] * (acc - m) * rsqrtf(v + EPSBN) + be1[c];
    h1[(long)r * HDIM + c] = fmaxf(y, 0.f);
}

// h2[r][c] = relu(BN(h1[r] . W2[c] + b2[c]))  — 64 blocks x 64 threads
__global__ void mlp2_kernel(const float* __restrict__ h1,
                            const float* __restrict__ W2, const float* __restrict__ b2,
                            const float* __restrict__ g2, const float* __restrict__ be2,
                            float* __restrict__ h2)
{
    const int c = blockIdx.x;   // 0..63
    const int r = threadIdx.x;  // 0..63
    float acc = b2[c];
    const float* w = W2 + (long)c * HDIM;
    const float* f = h1 + (long)r * HDIM;
#pragma unroll 8
    for (int i = 0; i < HDIM; i++) acc += f[i] * w[i];

    __shared__ float red[GNUM];
    red[r] = acc; __syncthreads();
    float m = 0.f;
    if (r == 0) { for (int i = 0; i < GNUM; i++) m += red[i]; red[0] = m / GNUM; }
    __syncthreads();
    m = red[0]; __syncthreads();
    red[r] = (acc - m) * (acc - m); __syncthreads();
    float v = 0.f;
    if (r == 0) { for (int i = 0; i < GNUM; i++) v += red[i]; red[0] = v / GNUM; }
    __syncthreads();
    v = red[0];
    const float y = g2[c] * (acc - m) * rsqrtf(v + EPSBN) + be2[c];
    h2[(long)r * (HDIM / 2) + c] = fmaxf(y, 0.f);
}

// out[r] = h2[r] . W3 + b3  — 1 block x 64 threads
__global__ void mlp3_kernel(const float* __restrict__ h2,
                            const float* __restrict__ W3, const float* __restrict__ b3,
                            float* __restrict__ out)
{
    const int r = threadIdx.x;
    float acc = b3[0];
#pragma unroll
    for (int i = 0; i < HDIM / 2; i++) acc += h2[(long)r * (HDIM / 2) + i] * W3[i];
    out[r] = acc;
}

// ---------------- launch -----------------
extern "C" void kernel_launch(void* const* d_in, const int* in_sizes, int n_in,
                              void* d_out, int out_size)
{
    const float* x     = (const float*)d_in[0];
    const int*   ei    = (const int*)d_in[1];
    const int*   batch = (const int*)d_in[2];
    const int N = in_sizes[0] / HDIM;
    const int E = in_sizes[1] / 2;

    const float* l0W[4], *l0b[4], *l1W[4], *l1b[4];
    for (int i = 0; i < 4; i++) {
        l0W[i] = (const float*)d_in[3 + 2 * i];
        l0b[i] = (const float*)d_in[4 + 2 * i];
        l1W[i] = (const float*)d_in[11 + 2 * i];
        l1b[i] = (const float*)d_in[12 + 2 * i];
    }
    const float* W1  = (const float*)d_in[19];
    const float* b1  = (const float*)d_in[20];
    const float* g1  = (const float*)d_in[21];
    const float* be1 = (const float*)d_in[22];
    const float* W2  = (const float*)d_in[23];
    const float* b2  = (const float*)d_in[24];
    const float* g2  = (const float*)d_in[25];
    const float* be2 = (const float*)d_in[26];
    const float* W3  = (const float*)d_in[27];
    const float* b3  = (const float*)d_in[28];
    float* out = (float*)d_out;

    float *pK, *pQ, *pV, *pH0, *pH1, *pPool, *pM1, *pM2;
    cudaGetSymbolAddress((void**)&pK,  g_K);
    cudaGetSymbolAddress((void**)&pQ,  g_Q);
    cudaGetSymbolAddress((void**)&pV,  g_V);
    cudaGetSymbolAddress((void**)&pH0, g_H0);
    cudaGetSymbolAddress((void**)&pH1, g_H1);
    cudaGetSymbolAddress((void**)&pPool, g_pool);
    cudaGetSymbolAddress((void**)&pM1, g_h1m);
    cudaGetSymbolAddress((void**)&pM2, g_h2m);

    const dim3 ggrid((N + 127) / 128, 8);
    const int eblocks = (E + 7) / 8;   // 8 warps/block, one warp per edge

    // layer 0
    gemm4_kernel<false><<<ggrid, 256>>>(x,
        l0W[0], l0W[1], l0W[2], l0W[3], l0b[0], l0b[1], l0b[2], l0b[3],
        pK, pQ, pV, pH0, N);
    edge_kernel<<<eblocks, 256>>>(ei, E, pK, pQ, pV, pH0);
    // layer 1 (relu on input)
    gemm4_kernel<true><<<ggrid, 256>>>(pH0,
        l1W[0], l1W[1], l1W[2], l1W[3], l1b[0], l1b[1], l1b[2], l1b[3],
        pK, pQ, pV, pH1, N);
    edge_kernel<<<eblocks, 256>>>(ei, E, pK, pQ, pV, pH1);
    // pooling + head
    pool_kernel<<<GNUM, HDIM>>>(pH1, batch, N, pPool);
    mlp1_kernel<<<HDIM, GNUM>>>(pPool, W1, b1, g1, be1, pM1);
    mlp2_kernel<<<HDIM / 2, GNUM>>>(pM1, W2, b2, g2, be2, pM2);
    mlp3_kernel<<<1, GNUM>>>(pM2, W3, b3, out);
}

// round 3
// speedup vs baseline: 1.7754x; 1.7754x over previous
#include <cuda_runtime.h>
#include <cuda_bf16.h>
#include <cstdint>

#define NNODE 50000
#define HDIM  128
#define GNUM  64
#define EPSBN 1e-5f

// ---------------- device scratch (no allocs allowed) ----------------
__device__ float g_K [NNODE * HDIM];
__device__ float g_Q [NNODE * HDIM];
__device__ float g_V [NNODE * HDIM];
__device__ float g_H0[NNODE * HDIM];
__device__ float g_H1[NNODE * HDIM];
__device__ float g_pool[GNUM * 2 * HDIM];
__device__ float g_h1m[GNUM * HDIM];
__device__ float g_h2m[GNUM * (HDIM / 2)];

// ---------------- bf16 split helpers ----------------
// x = hi + lo with hi = bf16(x), lo = bf16(x - hi). Packs 2 k-consecutive
// values into one u32 (low half = first element), matching HMMA frag layout.
__device__ __forceinline__ void split2(float x, float y, uint32_t& hi, uint32_t& lo) {
    __nv_bfloat162 h = __floats2bfloat162_rn(x, y);
    float hx = __bfloat162float(h.x);
    float hy = __bfloat162float(h.y);
    __nv_bfloat162 l = __floats2bfloat162_rn(x - hx, y - hy);
    hi = *(uint32_t*)&h;
    lo = *(uint32_t*)&l;
}

__device__ __forceinline__ void mma_bf16(float c[4], const uint32_t a[4], const uint32_t b[2]) {
    asm volatile(
        "mma.sync.aligned.m16n8k16.row.col.f32.bf16.bf16.f32 "
        "{%0,%1,%2,%3}, {%4,%5,%6,%7}, {%8,%9}, {%0,%1,%2,%3};"
        : "+f"(c[0]), "+f"(c[1]), "+f"(c[2]), "+f"(c[3])
        : "r"(a[0]), "r"(a[1]), "r"(a[2]), "r"(a[3]), "r"(b[0]), "r"(b[1]));
}

// ---------------- bf16x3 tensor-core GEMM: out = X @ W^T + b ----------------
// grid = (ceil(N/128), 4 weight-select), 256 threads (8 warps).
// BM=128, BN=128 (full H), BK=32. Warp tile 32x64 via m16n8k16, hi/lo split.
#define KP 20   // kpair stride (16 used + 4 pad) -> conflict-free frag loads
template <bool RELU_IN>
__global__ __launch_bounds__(256) void gemm_bf16x3_kernel(
    const float* __restrict__ X,
    const float* __restrict__ Wk, const float* __restrict__ Wq,
    const float* __restrict__ Wv, const float* __restrict__ Ws,
    const float* __restrict__ bk, const float* __restrict__ bq,
    const float* __restrict__ bv, const float* __restrict__ bs,
    float* __restrict__ oK, float* __restrict__ oQ,
    float* __restrict__ oV, float* __restrict__ oS, int N)
{
    const int sel = blockIdx.y;
    const float* W    = (sel == 0) ? Wk : (sel == 1) ? Wq : (sel == 2) ? Wv : Ws;
    const float* bias = (sel == 0) ? bk : (sel == 1) ? bq : (sel == 2) ? bv : bs;
    float*       out  = (sel == 0) ? oK : (sel == 1) ? oQ : (sel == 2) ? oV : oS;
    const int m0 = blockIdx.x * 128;

    __shared__ uint32_t AsH[128][KP], AsL[128][KP];   // [row][kpair]
    __shared__ uint32_t BsH[128][KP], BsL[128][KP];   // [n][kpair]

    const int tid  = threadIdx.x;
    const int wid  = tid >> 5;
    const int lane = tid & 31;
    const int wm  = wid & 3;        // 0..3 -> 32-row slab
    const int wn  = wid >> 2;       // 0..1 -> 64-col slab
    const int tp  = lane >> 2;      // groupID 0..7
    const int tig = lane & 3;       // 0..3

    float c[2][8][4];
#pragma unroll
    for (int mt = 0; mt < 2; mt++)
#pragma unroll
        for (int nt = 0; nt < 8; nt++)
#pragma unroll
            for (int j = 0; j < 4; j++) c[mt][nt][j] = 0.f;

    for (int k0 = 0; k0 < HDIM; k0 += 32) {
        // ---- load + split A tile: X[m0:m0+128][k0:k0+32] ----
#pragma unroll
        for (int it = 0; it < 4; it++) {
            const int idx = tid + it * 256;       // 0..1023
            const int row = idx >> 3;
            const int c4  = (idx & 7) * 4;        // k offset in tile
            const int gm  = m0 + row;
            float4 a = make_float4(0.f, 0.f, 0.f, 0.f);
            if (gm < N) a = *(const float4*)(X + (long)gm * HDIM + k0 + c4);
            if (RELU_IN) {
                a.x = fmaxf(a.x, 0.f); a.y = fmaxf(a.y, 0.f);
                a.z = fmaxf(a.z, 0.f); a.w = fmaxf(a.w, 0.f);
            }
            uint32_t h0, l0, h1, l1;
            split2(a.x, a.y, h0, l0);
            split2(a.z, a.w, h1, l1);
            const int kp = c4 >> 1;
            AsH[row][kp] = h0; AsH[row][kp + 1] = h1;
            AsL[row][kp] = l0; AsL[row][kp + 1] = l1;
        }
        // ---- load + split B tile: W[n][k0:k0+32] ----
#pragma unroll
        for (int it = 0; it < 4; it++) {
            const int idx = tid + it * 256;
            const int n   = idx >> 3;
            const int c4  = (idx & 7) * 4;
            const float4 b = *(const float4*)(W + (long)n * HDIM + k0 + c4);
            uint32_t h0, l0, h1, l1;
            split2(b.x, b.y, h0, l0);
            split2(b.z, b.w, h1, l1);
            const int kp = c4 >> 1;
            BsH[n][kp] = h0; BsH[n][kp + 1] = h1;
            BsL[n][kp] = l0; BsL[n][kp + 1] = l1;
        }
        __syncthreads();

#pragma unroll
        for (int ks = 0; ks < 2; ks++) {          // two k16 steps per BK=32
            const int kb = ks * 8;                // kpair base
            uint32_t ah[2][4], al[2][4];
#pragma unroll
            for (int mt = 0; mt < 2; mt++) {
                const int r = wm * 32 + mt * 16 + tp;
                ah[mt][0] = AsH[r    ][kb + tig];
                ah[mt][1] = AsH[r + 8][kb + tig];
                ah[mt][2] = AsH[r    ][kb + tig + 4];
                ah[mt][3] = AsH[r + 8][kb + tig + 4];
                al[mt][0] = AsL[r    ][kb + tig];
                al[mt][1] = AsL[r + 8][kb + tig];
                al[mt][2] = AsL[r    ][kb + tig + 4];
                al[mt][3] = AsL[r + 8][kb + tig + 4];
            }
            uint32_t bh[8][2], bl[8][2];
#pragma unroll
            for (int nt = 0; nt < 8; nt++) {
                const int col = wn * 64 + nt * 8 + tp;
                bh[nt][0] = BsH[col][kb + tig];
                bh[nt][1] = BsH[col][kb + tig + 4];
                bl[nt][0] = BsL[col][kb + tig];
                bl[nt][1] = BsL[col][kb + tig + 4];
            }
#pragma unroll
            for (int mt = 0; mt < 2; mt++)
#pragma unroll
                for (int nt = 0; nt < 8; nt++) {
                    mma_bf16(c[mt][nt], ah[mt], bl[nt]);   // cross terms
                    mma_bf16(c[mt][nt], al[mt], bh[nt]);
                    mma_bf16(c[mt][nt], ah[mt], bh[nt]);   // main term
                }
        }
        __syncthreads();
    }

    // epilogue: bias add + store (float2 per c-pair)
#pragma unroll
    for (int nt = 0; nt < 8; nt++) {
        const int col = wn * 64 + nt * 8 + 2 * tig;
        const float b0 = bias[col];
        const float b1 = bias[col + 1];
#pragma unroll
        for (int mt = 0; mt < 2; mt++) {
            const int r0 = m0 + wm * 32 + mt * 16 + tp;
            const int r1 = r0 + 8;
            if (r0 < N) {
                float2 v = make_float2(c[mt][nt][0] + b0, c[mt][nt][1] + b1);
                *(float2*)(out + (long)r0 * HDIM + col) = v;
            }
            if (r1 < N) {
                float2 v = make_float2(c[mt][nt][2] + b0, c[mt][nt][3] + b1);
                *(float2*)(out + (long)r1 * HDIM + col) = v;
            }
        }
    }
}

// ---------------- edge kernel: agg[dst] += sigmoid(K[dst]+Q[src]) * V[src] --
__global__ __launch_bounds__(256) void edge_kernel(
    const int* __restrict__ ei, int E,
    const float* __restrict__ K, const float* __restrict__ Q,
    const float* __restrict__ V, float* __restrict__ AGG)
{
    const int warp = (blockIdx.x * blockDim.x + threadIdx.x) >> 5;
    const int lane = threadIdx.x & 31;
    if (warp >= E) return;
    const int s = __ldg(ei + warp);
    const int d = __ldg(ei + E + warp);

    const float4 k4 = *(const float4*)(K + (long)d * HDIM + lane * 4);
    const float4 q4 = *(const float4*)(Q + (long)s * HDIM + lane * 4);
    const float4 v4 = *(const float4*)(V + (long)s * HDIM + lane * 4);

    const float g0 = 1.f / (1.f + __expf(-(k4.x + q4.x)));
    const float g1 = 1.f / (1.f + __expf(-(k4.y + q4.y)));
    const float g2 = 1.f / (1.f + __expf(-(k4.z + q4.z)));
    const float g3 = 1.f / (1.f + __expf(-(k4.w + q4.w)));

    float* o = AGG + (long)d * HDIM + lane * 4;
    asm volatile("red.global.add.v4.f32 [%0], {%1, %2, %3, %4};"
                 :: "l"(o), "f"(g0 * v4.x), "f"(g1 * v4.y),
                    "f"(g2 * v4.z), "f"(g3 * v4.w)
                 : "memory");
}

// ---------------- pooling: batch_index is sorted -> binary search segment ---
__device__ __forceinline__ int lower_bound_i(const int* a, int n, int v) {
    int lo = 0, hi = n;
    while (lo < hi) { int m = (lo + hi) >> 1; if (a[m] < v) lo = m + 1; else hi = m; }
    return lo;
}

// grid (G, 4), 128 threads: 4 row-lanes x 32 cols
__global__ void pool_kernel(const float* __restrict__ H,
                            const int* __restrict__ batch, int N,
                            float* __restrict__ pool)
{
    const int g    = blockIdx.x;
    const int c    = blockIdx.y * 32 + (threadIdx.x & 31);
    const int rloc = threadIdx.x >> 5;          // 0..3
    const int lo = lower_bound_i(batch, N, g);
    const int hi = lower_bound_i(batch, N, g + 1);
    float mx = -3.402823466e38f;
    float sm = 0.f;
    for (int n = lo + rloc; n < hi; n += 4) {
        const float x = H[(long)n * HDIM + c];
        mx = fmaxf(mx, x);
        sm += x;
    }
    __shared__ float smx[4][32], ssm[4][32];
    smx[rloc][threadIdx.x & 31] = mx;
    ssm[rloc][threadIdx.x & 31] = sm;
    __syncthreads();
    if (rloc == 0) {
        const int l = threadIdx.x & 31;
        mx = fmaxf(fmaxf(smx[0][l], smx[1][l]), fmaxf(smx[2][l], smx[3][l]));
        sm = ssm[0][l] + ssm[1][l] + ssm[2][l] + ssm[3][l];
        const int cnt = hi - lo;
        pool[g * (2 * HDIM) + c]        = (cnt > 0) ? mx : 0.f;
        pool[g * (2 * HDIM) + HDIM + c] = sm / fmaxf((float)cnt, 1.f);
    }
}

// ---------------- MLP head ----------------
__global__ void mlp1_kernel(const float* __restrict__ pool,
                            const float* __restrict__ W1, const float* __restrict__ b1,
                            const float* __restrict__ g1, const float* __restrict__ be1,
                            float* __restrict__ h1)
{
    const int c = blockIdx.x;   // 0..127
    const int r = threadIdx.x;  // 0..63
    float acc = b1[c];
    const float* w = W1 + (long)c * (2 * HDIM);
    const float* f = pool + (long)r * (2 * HDIM);
#pragma unroll 8
    for (int i = 0; i < 2 * HDIM; i++) acc += f[i] * w[i];

    __shared__ float red[GNUM];
    red[r] = acc; __syncthreads();
    float m = 0.f;
    if (r == 0) { for (int i = 0; i < GNUM; i++) m += red[i]; red[0] = m / GNUM; }
    __syncthreads();
    m = red[0]; __syncthreads();
    red[r] = (acc - m) * (acc - m); __syncthreads();
    float v = 0.f;
    if (r == 0) { for (int i = 0; i < GNUM; i++) v += red[i]; red[0] = v / GNUM; }
    __syncthreads();
    v = red[0];
    const float y = g1[c] * (acc - m) * rsqrtf(v + EPSBN) + be1[c];
    h1[(long)r * HDIM + c] = fmaxf(y, 0.f);
}

__global__ void mlp2_kernel(const float* __restrict__ h1,
                            const float* __restrict__ W2, const float* __restrict__ b2,
                            const float* __restrict__ g2, const float* __restrict__ be2,
                            float* __restrict__ h2)
{
    const int c = blockIdx.x;   // 0..63
    const int r = threadIdx.x;  // 0..63
    float acc = b2[c];
    const float* w = W2 + (long)c * HDIM;
    const float* f = h1 + (long)r * HDIM;
#pragma unroll 8
    for (int i = 0; i < HDIM; i++) acc += f[i] * w[i];

    __shared__ float red[GNUM];
    red[r] = acc; __syncthreads();
    float m = 0.f;
    if (r == 0) { for (int i = 0; i < GNUM; i++) m += red[i]; red[0] = m / GNUM; }
    __syncthreads();
    m = red[0]; __syncthreads();
    red[r] = (acc - m) * (acc - m); __syncthreads();
    float v = 0.f;
    if (r == 0) { for (int i = 0; i < GNUM; i++) v += red[i]; red[0] = v / GNUM; }
    __syncthreads();
    v = red[0];
    const float y = g2[c] * (acc - m) * rsqrtf(v + EPSBN) + be2[c];
    h2[(long)r * (HDIM / 2) + c] = fmaxf(y, 0.f);
}

__global__ void mlp3_kernel(const float* __restrict__ h2,
                            const float* __restrict__ W3, const float* __restrict__ b3,
                            float* __restrict__ out)
{
    const int r = threadIdx.x;
    float acc = b3[0];
#pragma unroll
    for (int i = 0; i < HDIM / 2; i++) acc += h2[(long)r * (HDIM / 2) + i] * W3[i];
    out[r] = acc;
}

// ---------------- launch -----------------
extern "C" void kernel_launch(void* const* d_in, const int* in_sizes, int n_in,
                              void* d_out, int out_size)
{
    const float* x     = (const float*)d_in[0];
    const int*   ei    = (const int*)d_in[1];
    const int*   batch = (const int*)d_in[2];
    const int N = in_sizes[0] / HDIM;
    const int E = in_sizes[1] / 2;

    const float* l0W[4], *l0b[4], *l1W[4], *l1b[4];
    for (int i = 0; i < 4; i++) {
        l0W[i] = (const float*)d_in[3 + 2 * i];
        l0b[i] = (const float*)d_in[4 + 2 * i];
        l1W[i] = (const float*)d_in[11 + 2 * i];
        l1b[i] = (const float*)d_in[12 + 2 * i];
    }
    const float* W1  = (const float*)d_in[19];
    const float* b1  = (const float*)d_in[20];
    const float* g1  = (const float*)d_in[21];
    const float* be1 = (const float*)d_in[22];
    const float* W2  = (const float*)d_in[23];
    const float* b2  = (const float*)d_in[24];
    const float* g2  = (const float*)d_in[25];
    const float* be2 = (const float*)d_in[26];
    const float* W3  = (const float*)d_in[27];
    const float* b3  = (const float*)d_in[28];
    float* out = (float*)d_out;

    float *pK, *pQ, *pV, *pH0, *pH1, *pPool, *pM1, *pM2;
    cudaGetSymbolAddress((void**)&pK,  g_K);
    cudaGetSymbolAddress((void**)&pQ,  g_Q);
    cudaGetSymbolAddress((void**)&pV,  g_V);
    cudaGetSymbolAddress((void**)&pH0, g_H0);
    cudaGetSymbolAddress((void**)&pH1, g_H1);
    cudaGetSymbolAddress((void**)&pPool, g_pool);
    cudaGetSymbolAddress((void**)&pM1, g_h1m);
    cudaGetSymbolAddress((void**)&pM2, g_h2m);

    const dim3 ggrid((N + 127) / 128, 4);
    const int eblocks = (E + 7) / 8;   // 8 warps/block, one warp per edge

    // layer 0
    gemm_bf16x3_kernel<false><<<ggrid, 256>>>(x,
        l0W[0], l0W[1], l0W[2], l0W[3], l0b[0], l0b[1], l0b[2], l0b[3],
        pK, pQ, pV, pH0, N);
    edge_kernel<<<eblocks, 256>>>(ei, E, pK, pQ, pV, pH0);
    // layer 1 (relu on input)
    gemm_bf16x3_kernel<true><<<ggrid, 256>>>(pH0,
        l1W[0], l1W[1], l1W[2], l1W[3], l1b[0], l1b[1], l1b[2], l1b[3],
        pK, pQ, pV, pH1, N);
    edge_kernel<<<eblocks, 256>>>(ei, E, pK, pQ, pV, pH1);
    // pooling + head
    pool_kernel<<<dim3(GNUM, 4), 128>>>(pH1, batch, N, pPool);
    mlp1_kernel<<<HDIM, GNUM>>>(pPool, W1, b1, g1, be1, pM1);
    mlp2_kernel<<<HDIM / 2, GNUM>>>(pM1, W2, b2, g2, be2, pM2);
    mlp3_kernel<<<1, GNUM>>>(pM2, W3, b3, out);
}